// round 9
// baseline (speedup 1.0000x reference)
#include <cuda_runtime.h>
#include <cuda_bf16.h>

// DetectionLoss, single fused kernel, v7.
// 96 blocks x 64 threads, one WARP per (batch,scale) item, 2 targets/lane
// (lane l -> targets l and l+32; lanes 28-31 have no 2nd target).
// Warp-autonomous: warp-private smem + __syncwarp only in the work path.
// REDG partials into 12 global sums; one 96-arrival counter; last block
// finalizes from 12 floats.

#define NCH   11
#define NCLS  6
#define NT    60
#define NB    64
#define NBLK  96
#define PAD_SENTINEL 0x40000000
#define NO_B_CELL    0x20000000

__device__ float    g_sum[12];     // [scale*4 + {cls,iou,inner,np}]
__device__ unsigned g_done;

__device__ __forceinline__ float iou_scaled(
    float px, float py, float pw, float ph,
    float tx, float ty, float tw, float th, float sc)
{
    float pw2 = pw * sc * 0.5f, ph2 = ph * sc * 0.5f;
    float tw2 = tw * sc * 0.5f, th2 = th * sc * 0.5f;
    float x11 = px - pw2, x12 = px + pw2;
    float y11 = py - ph2, y12 = py + ph2;
    float x21 = tx - tw2, x22 = tx + tw2;
    float y21 = ty - th2, y22 = ty + th2;
    float iw = fmaxf(fminf(x12, x22) - fmaxf(x11, x21), 0.0f);
    float ih = fmaxf(fminf(y12, y22) - fmaxf(y11, y21), 0.0f);
    float inter = iw * ih;
    float a1 = (x12 - x11) * (y12 - y11);
    float a2 = (x22 - x21) * (y22 - y21);
    return inter / (a1 + a2 - inter + 1e-7f);
}

__device__ __forceinline__ float bce6(const float* z, unsigned cm)
{
    float bce = 0.0f;
    #pragma unroll
    for (int c = 0; c < NCLS; ++c) {
        float tt = ((cm >> c) & 1u) ? 1.0f : 0.0f;
        bce += fmaxf(z[c], 0.0f) - z[c] * tt
             + __logf(1.0f + __expf(-fabsf(z[c])));
    }
    return bce;
}

__global__ void __launch_bounds__(64, 16) dl_fused_kernel(
    const float* __restrict__ p3,
    const float* __restrict__ p4,
    const float* __restrict__ p5,
    const int*   __restrict__ tcls,
    const float* __restrict__ tbox,
    float*       __restrict__ out)
{
    const int t  = threadIdx.x;
    const int w  = t >> 5;                   // warp in block (0/1)
    const int l  = t & 31;                   // lane
    const int id = blockIdx.x * 2 + w;       // item 0..191
    const int s  = id >> 6;                  // scale
    const int b  = id & 63;                  // batch

    const float* pred;
    int W;
    if      (s == 0) { pred = p3; W = 160; }
    else if (s == 1) { pred = p4; W = 80;  }
    else             { pred = p5; W = 40;  }
    const int HW = W * W;
    const float* bbase = pred + b * NCH * HW;

    __shared__ int s_pk[2][64];              // warp-private packed arrays

    // ---- target A (index l, always valid since l < 32 <= 60) ----
    int   clsA = tcls[b * NT + l];
    float4 bxA = reinterpret_cast<const float4*>(tbox)[b * NT + l];
    int gxA = min(max((int)(bxA.x * (float)W), 0), W - 1);
    int gyA = min(max((int)(bxA.y * (float)W), 0), W - 1);
    int cellA = gyA * W + gxA;
    s_pk[w][l] = (cellA << 6) | clsA;

    // ---- target B (index 32+l, valid for l < 28) ----
    const bool hasB = (l < NT - 32);
    int   cellB = 0;
    float4 bxB  = make_float4(0.f, 0.f, 0.f, 0.f);
    if (hasB) {
        int   clsB = tcls[b * NT + 32 + l];
        bxB = reinterpret_cast<const float4*>(tbox)[b * NT + 32 + l];
        int gxB = min(max((int)(bxB.x * (float)W), 0), W - 1);
        int gyB = min(max((int)(bxB.y * (float)W), 0), W - 1);
        cellB = gyB * W + gxB;
        s_pk[w][32 + l] = (cellB << 6) | clsB;
    } else {
        s_pk[w][32 + l] = PAD_SENTINEL;      // matches no real cell
    }

    // ---- issue all pred loads up front (MLP up to 20) ----
    float zA[NCLS], pxA, pyA, pwA, phA;
    {
        const float* base = bbase + cellA;
        #pragma unroll
        for (int c = 0; c < NCLS; ++c) zA[c] = __ldg(base + c * HW);
        pxA = __ldg(base + 7  * HW);
        pyA = __ldg(base + 8  * HW);
        pwA = __ldg(base + 9  * HW);
        phA = __ldg(base + 10 * HW);
    }
    float zB[NCLS] = {0}, pxB = 0.f, pyB = 0.f, pwB = 0.f, phB = 0.f;
    if (hasB) {
        const float* base = bbase + cellB;
        #pragma unroll
        for (int c = 0; c < NCLS; ++c) zB[c] = __ldg(base + c * HW);
        pxB = __ldg(base + 7  * HW);
        pyB = __ldg(base + 8  * HW);
        pwB = __ldg(base + 9  * HW);
        phB = __ldg(base + 10 * HW);
    }

    __syncwarp();

    // ---- register-resident scan of all 64 entries for both cells ----
    const int c0 = cellA << 6;
    const int c1 = hasB ? (cellB << 6) : NO_B_CELL;   // matches nothing
    unsigned cm0 = 0u, cm1 = 0u;
    int bad0 = 0, bad1 = 0;
    const int myA = l, myB = 32 + l;

    const int4* pk4 = reinterpret_cast<const int4*>(s_pk[w]);
    #pragma unroll
    for (int i = 0; i < 16; ++i) {
        int4 q = pk4[i];
        int idx = i * 4;
        #pragma unroll
        for (int j = 0; j < 4; ++j) {
            int v = (j == 0) ? q.x : (j == 1) ? q.y : (j == 2) ? q.z : q.w;
            int e = v & ~63;
            if (e == c0) { cm0 |= 1u << (v & 63); bad0 |= (idx + j > myA); }
            if (e == c1) { cm1 |= 1u << (v & 63); bad1 |= (idx + j > myB); }
        }
    }

    // ---- losses ----
    float cls_p = 0.0f, iou_p = 0.0f, inner_p = 0.0f, np = 0.0f;
    if (!bad0) {     // A owns its cell
        cls_p   += bce6(zA, cm0);
        iou_p   += 1.0f - iou_scaled(pxA, pyA, pwA, phA, bxA.x, bxA.y, bxA.z, bxA.w, 1.0f);
        inner_p += 1.0f - iou_scaled(pxA, pyA, pwA, phA, bxA.x, bxA.y, bxA.z, bxA.w, 0.7f);
        np      += 1.0f;
    }
    if (hasB && !bad1) {
        cls_p   += bce6(zB, cm1);
        iou_p   += 1.0f - iou_scaled(pxB, pyB, pwB, phB, bxB.x, bxB.y, bxB.z, bxB.w, 1.0f);
        inner_p += 1.0f - iou_scaled(pxB, pyB, pwB, phB, bxB.x, bxB.y, bxB.z, bxB.w, 0.7f);
        np      += 1.0f;
    }

    // ---- warp reduce + REDG ----
    #pragma unroll
    for (int o = 16; o > 0; o >>= 1) {
        cls_p   += __shfl_down_sync(0xffffffffu, cls_p,   o);
        iou_p   += __shfl_down_sync(0xffffffffu, iou_p,   o);
        inner_p += __shfl_down_sync(0xffffffffu, inner_p, o);
        np      += __shfl_down_sync(0xffffffffu, np,      o);
    }
    if (l == 0) {
        atomicAdd(&g_sum[s * 4 + 0], cls_p);
        atomicAdd(&g_sum[s * 4 + 1], iou_p);
        atomicAdd(&g_sum[s * 4 + 2], inner_p);
        atomicAdd(&g_sum[s * 4 + 3], np);
        __threadfence();
    }
    __syncthreads();

    if (t == 0) {
        unsigned d = atomicAdd(&g_done, 1u);
        if (d == NBLK - 1) {
            // Every block fenced its REDGs before its counter bump; final
            // count observed => sums complete in L2.
            float m[12];
            #pragma unroll
            for (int k = 0; k < 12; ++k)
                m[k] = ((const volatile float*)g_sum)[k];

            float cls_total = 0.0f, box_total = 0.0f;
            #pragma unroll
            for (int k2 = 0; k2 < 3; ++k2) {
                float inv = 1.0f / (m[k2 * 4 + 3] + 1e-8f);
                cls_total += m[k2 * 4 + 0] * inv;
                // box = 0.5*iou + 0.5*(0.5*iou + 0.5*inner)
                box_total += 0.75f * (m[k2 * 4 + 1] * inv)
                           + 0.25f * (m[k2 * 4 + 2] * inv);
            }
            cls_total *= (1.0f / 3.0f);
            box_total *= (1.0f / 3.0f);
            out[0] = 0.5f * cls_total + 7.5f * box_total;  // CLS_W, BOX_W
            out[1] = cls_total;
            out[2] = box_total;

            // Reset for next graph replay (kernel-end membar publishes).
            #pragma unroll
            for (int k = 0; k < 12; ++k) g_sum[k] = 0.0f;
            g_done = 0u;
        }
    }
}

extern "C" void kernel_launch(void* const* d_in, const int* in_sizes, int n_in,
                              void* d_out, int out_size)
{
    const float* p3   = (const float*)d_in[0];
    const float* p4   = (const float*)d_in[1];
    const float* p5   = (const float*)d_in[2];
    const int*   tcls = (const int*)  d_in[3];
    const float* tbox = (const float*)d_in[4];
    float*       out  = (float*)d_out;

    dl_fused_kernel<<<NBLK, 64>>>(p3, p4, p5, tcls, tbox, out);
}

// round 10
// speedup vs baseline: 1.1956x; 1.1956x over previous
#include <cuda_runtime.h>
#include <cuda_bf16.h>

// DetectionLoss, single fused kernel, v8 (= R7 best front + REDG tail).
// Grid (64 batches x 3 scales) x 64 threads, one target per thread.
// Sparse evaluation, register-resident collision scan, hierarchical
// completion counters, REDG accumulation into 12 contiguous sums,
// 12-float last-block finalize.

#define NCH   11
#define NCLS  6
#define NT    60
#define NB    64

__device__ float    g_sum[12];         // [scale*4 + {cls,iou,inner,np}] one line
__device__ unsigned g_done1[NB][32];   // per-batch counter, 128B padded
__device__ unsigned g_done2;           // root counter (NB arrivals)

__device__ __forceinline__ float iou_scaled(
    float px, float py, float pw, float ph,
    float tx, float ty, float tw, float th, float sc)
{
    float pw2 = pw * sc * 0.5f, ph2 = ph * sc * 0.5f;
    float tw2 = tw * sc * 0.5f, th2 = th * sc * 0.5f;
    float x11 = px - pw2, x12 = px + pw2;
    float y11 = py - ph2, y12 = py + ph2;
    float x21 = tx - tw2, x22 = tx + tw2;
    float y21 = ty - th2, y22 = ty + th2;
    float iw = fmaxf(fminf(x12, x22) - fmaxf(x11, x21), 0.0f);
    float ih = fmaxf(fminf(y12, y22) - fmaxf(y11, y21), 0.0f);
    float inter = iw * ih;
    float a1 = (x12 - x11) * (y12 - y11);
    float a2 = (x22 - x21) * (y22 - y21);
    return inter / (a1 + a2 - inter + 1e-7f);
}

__global__ void __launch_bounds__(64, 16) dl_fused_kernel(
    const float* __restrict__ p3,
    const float* __restrict__ p4,
    const float* __restrict__ p5,
    const int*   __restrict__ tcls,
    const float* __restrict__ tbox,
    float*       __restrict__ out)
{
    const int b   = blockIdx.x;
    const int s   = blockIdx.y;
    const int tid = threadIdx.x;

    const float* pred;
    int W;
    if      (s == 0) { pred = p3; W = 160; }
    else if (s == 1) { pred = p4; W = 80;  }
    else             { pred = p5; W = 40;  }

    __shared__ int4  s_pk4[15];      // packed (cell<<6)|cls, 60 entries
    __shared__ float s_red[2][4];    // 2-warp partials
    __shared__ int   s_last;

    float tx = 0.f, ty = 0.f, tw = 0.f, th = 0.f;
    int   cell = -1;
    float z[NCLS], px = 0.f, py = 0.f, pw = 0.f, ph = 0.f;

    if (tid < NT) {
        int   cls = tcls[b * NT + tid];
        float4 bx = reinterpret_cast<const float4*>(tbox)[b * NT + tid];
        tx = bx.x; ty = bx.y; tw = bx.z; th = bx.w;
        int gx = (int)(tx * (float)W); gx = min(max(gx, 0), W - 1);
        int gy = (int)(ty * (float)W); gy = min(max(gy, 0), W - 1);
        cell = gy * W + gx;
        reinterpret_cast<int*>(&s_pk4[0])[tid] = (cell << 6) | cls;

        // 32-bit offsets (max index < 2^25); all 10 scattered loads issued
        // up front (MLP=10) so the DRAM/L2 latency overlaps the scan.
        const int HW = W * W;
        const float* base = pred + b * NCH * HW + cell;
        #pragma unroll
        for (int c = 0; c < NCLS; ++c) z[c] = __ldg(base + c * HW);
        px = __ldg(base + 7  * HW);
        py = __ldg(base + 8  * HW);
        pw = __ldg(base + 9  * HW);
        ph = __ldg(base + 10 * HW);
    }
    __syncthreads();

    float cls_p = 0.0f, iou_p = 0.0f, inner_p = 0.0f, np = 0.0f;

    if (tid < NT) {
        // Register-resident scan over all 60 packed entries (broadcast LDS.128).
        const int cellsh = cell << 6;
        unsigned cm  = 0u;   // union of one-hot classes at this cell
        int      bad = 0;    // some later target claims this cell
        #pragma unroll
        for (int i = 0; i < 15; ++i) {
            int4 q = s_pk4[i];
            int idx = i * 4;
            if (((q.x ^ cellsh) & ~63) == 0) { cm |= 1u << (q.x & 63); bad |= (idx + 0 > tid); }
            if (((q.y ^ cellsh) & ~63) == 0) { cm |= 1u << (q.y & 63); bad |= (idx + 1 > tid); }
            if (((q.z ^ cellsh) & ~63) == 0) { cm |= 1u << (q.z & 63); bad |= (idx + 2 > tid); }
            if (((q.w ^ cellsh) & ~63) == 0) { cm |= 1u << (q.w & 63); bad |= (idx + 3 > tid); }
        }

        if (!bad) {   // owner = last target mapping to this cell
            float bce = 0.0f;
            #pragma unroll
            for (int c = 0; c < NCLS; ++c) {
                float tt = ((cm >> c) & 1u) ? 1.0f : 0.0f;
                bce += fmaxf(z[c], 0.0f) - z[c] * tt
                     + __logf(1.0f + __expf(-fabsf(z[c])));
            }
            float iou   = iou_scaled(px, py, pw, ph, tx, ty, tw, th, 1.0f);
            float inner = iou_scaled(px, py, pw, ph, tx, ty, tw, th, 0.7f);
            cls_p = bce;  iou_p = 1.0f - iou;  inner_p = 1.0f - inner;  np = 1.0f;
        }
    }

    // Warp shfl reduce, combine the 2 warps in smem.
    #pragma unroll
    for (int o = 16; o > 0; o >>= 1) {
        cls_p   += __shfl_down_sync(0xffffffffu, cls_p,   o);
        iou_p   += __shfl_down_sync(0xffffffffu, iou_p,   o);
        inner_p += __shfl_down_sync(0xffffffffu, inner_p, o);
        np      += __shfl_down_sync(0xffffffffu, np,      o);
    }
    const int warp = tid >> 5;
    if ((tid & 31) == 0) {
        s_red[warp][0] = cls_p;  s_red[warp][1] = iou_p;
        s_red[warp][2] = inner_p; s_red[warp][3] = np;
    }
    __syncthreads();

    // REDG partials into the 12 contiguous sums, then hierarchical
    // completion: per-batch counter (3 arrivals, 64 in parallel) -> root.
    if (tid == 0) {
        atomicAdd(&g_sum[s * 4 + 0], s_red[0][0] + s_red[1][0]);
        atomicAdd(&g_sum[s * 4 + 1], s_red[0][1] + s_red[1][1]);
        atomicAdd(&g_sum[s * 4 + 2], s_red[0][2] + s_red[1][2]);
        atomicAdd(&g_sum[s * 4 + 3], s_red[0][3] + s_red[1][3]);
        __threadfence();
        int lastflag = 0;
        unsigned d1 = atomicAdd(&g_done1[b][0], 1u);
        if (d1 == 2u) {                       // batch-last block
            atomicExch(&g_done1[b][0], 0u);   // reset own counter (we are 3rd)
            unsigned d2 = atomicAdd(&g_done2, 1u);
            lastflag = (d2 == NB - 1);
        }
        s_last = lastflag;

        if (lastflag) {
            // Every block fenced its REDGs before its counter bumps; final
            // root count observed => the 12 sums are complete in L2 (one
            // cache line -> a single round trip).
            float m[12];
            #pragma unroll
            for (int k = 0; k < 12; ++k)
                m[k] = ((const volatile float*)g_sum)[k];

            float cls_total = 0.0f, box_total = 0.0f;
            #pragma unroll
            for (int k2 = 0; k2 < 3; ++k2) {
                float inv = 1.0f / (m[k2 * 4 + 3] + 1e-8f);
                cls_total += m[k2 * 4 + 0] * inv;
                // box = 0.5*iou + 0.5*(0.5*iou + 0.5*inner)
                box_total += 0.75f * (m[k2 * 4 + 1] * inv)
                           + 0.25f * (m[k2 * 4 + 2] * inv);
            }
            cls_total *= (1.0f / 3.0f);
            box_total *= (1.0f / 3.0f);
            out[0] = 0.5f * cls_total + 7.5f * box_total;  // CLS_W, BOX_W
            out[1] = cls_total;
            out[2] = box_total;

            // Reset for next graph replay (kernel-end membar publishes).
            #pragma unroll
            for (int k = 0; k < 12; ++k) g_sum[k] = 0.0f;
            g_done2 = 0u;
        }
    }
}

extern "C" void kernel_launch(void* const* d_in, const int* in_sizes, int n_in,
                              void* d_out, int out_size)
{
    const float* p3   = (const float*)d_in[0];
    const float* p4   = (const float*)d_in[1];
    const float* p5   = (const float*)d_in[2];
    const int*   tcls = (const int*)  d_in[3];
    const float* tbox = (const float*)d_in[4];
    float*       out  = (float*)d_out;

    dim3 grid(NB, 3);
    dl_fused_kernel<<<grid, 64>>>(p3, p4, p5, tcls, tbox, out);
}